// round 7
// baseline (speedup 1.0000x reference)
#include <cuda_runtime.h>
#include <cstdint>

// SSIM loss, NCHW (32,3,512,512) fp32, 3x3 box, reflect pad 1, scalar mean.
// R6: row-PAIR emission sharing the middle vertical partial sums (B+C terms)
// between adjacent output rows (-11% fma ops, 2 independent SSIM chains per
// stage for ILP); RPB=64 -> 768 blocks = ~single wave; packed f32x2 math;
// pipelined 4-buffer row ring; last-block fp64 reduce.

#define H 512
#define W 512
#define PLANES (32 * 3)
#define RPB 64
#define BLOCKS_X (H / RPB)           // 8
#define NBLOCKS (BLOCKS_X * PLANES)  // 768

typedef unsigned long long u64;

__device__ float g_partials[NBLOCKS];
__device__ unsigned int g_count = 0;

__device__ __forceinline__ u64 pk(float lo, float hi) {
    u64 r; asm("mov.b64 %0, {%1, %2};" : "=l"(r) : "f"(lo), "f"(hi)); return r;
}
__device__ __forceinline__ void unpk(u64 v, float& lo, float& hi) {
    asm("mov.b64 {%0, %1}, %2;" : "=f"(lo), "=f"(hi) : "l"(v));
}
__device__ __forceinline__ u64 add2(u64 a, u64 b) {
    u64 d; asm("add.rn.f32x2 %0, %1, %2;" : "=l"(d) : "l"(a), "l"(b)); return d;
}
__device__ __forceinline__ u64 sub2(u64 a, u64 b) {
    u64 d; asm("sub.rn.f32x2 %0, %1, %2;" : "=l"(d) : "l"(a), "l"(b)); return d;
}
__device__ __forceinline__ u64 mul2(u64 a, u64 b) {
    u64 d; asm("mul.rn.f32x2 %0, %1, %2;" : "=l"(d) : "l"(a), "l"(b)); return d;
}
__device__ __forceinline__ u64 fma2(u64 a, u64 b, u64 c) {
    u64 d; asm("fma.rn.f32x2 %0, %1, %2, %3;" : "=l"(d) : "l"(a), "l"(b), "l"(c)); return d;
}
__device__ __forceinline__ float rcpf(float x) {
    float r; asm("rcp.approx.ftz.f32 %0, %1;" : "=f"(r) : "f"(x)); return r;
}

__device__ __forceinline__ int refl(int i) {
    if (i < 0) return -i;
    if (i > H - 1) return 2 * (H - 1) - i;
    return i;
}

// Raw row: packed x,y for 4 columns + halo scalars (lanes 0/31 only).
struct RowR { u64 X0, X1, Y0, Y1; float hX, hY; };

struct K { u64 twop, n2p, p18, p9, c1p, c2p, nhp, php; };

__device__ __forceinline__ void load_row(RowR& R,
                                         const float* __restrict__ xp,
                                         const float* __restrict__ yp,
                                         int rr, int base, int hcol, bool doHalo) {
    const float4 xv = *reinterpret_cast<const float4*>(xp + rr * W + base);
    const float4 yv = *reinterpret_cast<const float4*>(yp + rr * W + base);
    R.X0 = pk(xv.x, xv.y); R.X1 = pk(xv.z, xv.w);
    R.Y0 = pk(yv.x, yv.y); R.Y1 = pk(yv.z, yv.w);
    if (doHalo) {
        R.hX = __ldg(xp + rr * W + hcol);
        R.hY = __ldg(yp + rr * W + hcol);
    }
}

// SSIM on raw 3x3 window sums (packed pixel pair); /9 factors cancel:
//   n/d = (2A+81C1)(18 Sxy - 2A + 81C2) / ((B+C+81C1)(9(Sxx+Syy)-B-C+81C2))
__device__ __forceinline__ u64 ssim2(u64 Sx, u64 Sy, u64 Sxx, u64 Syy, u64 Sxy,
                                     const K& k) {
    u64 A  = mul2(Sx, Sy);
    u64 B  = mul2(Sx, Sx);
    u64 C  = mul2(Sy, Sy);
    u64 n1 = fma2(A, k.twop, k.c1p);
    u64 t  = fma2(A, k.n2p,  k.c2p);
    u64 n2 = fma2(Sxy, k.p18, t);
    u64 n  = mul2(n1, n2);
    u64 BC = add2(B, C);
    u64 d1 = add2(BC, k.c1p);
    u64 u  = sub2(k.c2p, BC);
    u64 d2 = fma2(add2(Sxx, Syy), k.p9, u);
    u64 d  = mul2(d1, d2);
    float dd0, dd1; unpk(d, dd0, dd1);
    u64 rp = pk(rcpf(dd0), rcpf(dd1));
    u64 q  = mul2(n, rp);
    return fma2(q, k.nhp, k.php);
}

// Horizontal packed 3-sum for one quantity; inputs v0 (px 0,1), v1 (px 2,3), halo hv.
#define HQ2(q, v0, v1, hv)                                                    \
    float a0_##q, a1_##q, a2_##q, a3_##q;                                     \
    unpk(v0, a0_##q, a1_##q);                                                 \
    unpk(v1, a2_##q, a3_##q);                                                 \
    float lv_##q = __shfl_up_sync(0xffffffffu, a3_##q, 1);                    \
    float rv_##q = __shfl_down_sync(0xffffffffu, a0_##q, 1);                  \
    if (lane == 0)  lv_##q = (wseg == 0) ? a1_##q : hv;                       \
    if (lane == 31) rv_##q = (wseg == 3) ? a2_##q : hv;                       \
    u64 mid_##q = pk(a1_##q, a2_##q);                                         \
    u64 h0_##q = add2(add2(pk(lv_##q, a0_##q), v0), mid_##q);                 \
    u64 h1_##q = add2(add2(mid_##q, v1), pk(a3_##q, rv_##q));

// Horizontal 3-sum + SSIM for one output row given its vertical sums.
__device__ __forceinline__ u64 row_ssim(
    u64 vX0, u64 vX1, u64 vY0, u64 vY1, u64 vXX0, u64 vXX1,
    u64 vYY0, u64 vYY1, u64 vXY0, u64 vXY1,
    float hvX, float hvY, float hvXX, float hvYY, float hvXY,
    int lane, int wseg, const K& k)
{
    HQ2(X,  vX0,  vX1,  hvX)
    HQ2(Y,  vY0,  vY1,  hvY)
    HQ2(XX, vXX0, vXX1, hvXX)
    HQ2(YY, vYY0, vYY1, hvYY)
    HQ2(XY, vXY0, vXY1, hvXY)
    u64 s0 = ssim2(h0_X, h0_Y, h0_XX, h0_YY, h0_XY, k);
    u64 s1 = ssim2(h1_X, h1_Y, h1_XX, h1_YY, h1_XY, k);
    return add2(s0, s1);
}

// Emit two adjacent output rows: row r from (A,B,C), row r+1 from (B,C,D).
// The middle-pair partial sums over (B,C) are shared between the two rows.
__device__ __forceinline__ void emit_pair(const RowR& A, const RowR& B,
                                          const RowR& C, const RowR& D,
                                          u64& acc0, u64& acc1,
                                          int lane, int wseg, const K& k) {
    // shared middle partial sums over rows B,C
    u64 sX0  = add2(B.X0, C.X0),  sX1  = add2(B.X1, C.X1);
    u64 sY0  = add2(B.Y0, C.Y0),  sY1  = add2(B.Y1, C.Y1);
    u64 sXX0 = fma2(B.X0, B.X0, mul2(C.X0, C.X0));
    u64 sXX1 = fma2(B.X1, B.X1, mul2(C.X1, C.X1));
    u64 sYY0 = fma2(B.Y0, B.Y0, mul2(C.Y0, C.Y0));
    u64 sYY1 = fma2(B.Y1, B.Y1, mul2(C.Y1, C.Y1));
    u64 sXY0 = fma2(B.X0, B.Y0, mul2(C.X0, C.Y0));
    u64 sXY1 = fma2(B.X1, B.Y1, mul2(C.X1, C.Y1));

    float shX  = B.hX + C.hX;
    float shY  = B.hY + C.hY;
    float shXX = fmaf(B.hX, B.hX, C.hX * C.hX);
    float shYY = fmaf(B.hY, B.hY, C.hY * C.hY);
    float shXY = fmaf(B.hX, B.hY, C.hX * C.hY);

    // row r: add row A
    acc0 = add2(acc0, row_ssim(
        add2(A.X0, sX0), add2(A.X1, sX1),
        add2(A.Y0, sY0), add2(A.Y1, sY1),
        fma2(A.X0, A.X0, sXX0), fma2(A.X1, A.X1, sXX1),
        fma2(A.Y0, A.Y0, sYY0), fma2(A.Y1, A.Y1, sYY1),
        fma2(A.X0, A.Y0, sXY0), fma2(A.X1, A.Y1, sXY1),
        A.hX + shX, A.hY + shY,
        fmaf(A.hX, A.hX, shXX), fmaf(A.hY, A.hY, shYY), fmaf(A.hX, A.hY, shXY),
        lane, wseg, k));

    // row r+1: add row D
    acc1 = add2(acc1, row_ssim(
        add2(D.X0, sX0), add2(D.X1, sX1),
        add2(D.Y0, sY0), add2(D.Y1, sY1),
        fma2(D.X0, D.X0, sXX0), fma2(D.X1, D.X1, sXX1),
        fma2(D.Y0, D.Y0, sYY0), fma2(D.Y1, D.Y1, sYY1),
        fma2(D.X0, D.Y0, sXY0), fma2(D.X1, D.Y1, sXY1),
        D.hX + shX, D.hY + shY,
        fmaf(D.hX, D.hX, shXX), fmaf(D.hY, D.hY, shYY), fmaf(D.hX, D.hY, shXY),
        lane, wseg, k));
}

__global__ __launch_bounds__(128)
void ssim_main(const float* __restrict__ x, const float* __restrict__ y,
               float* __restrict__ out) {
    const int tid   = threadIdx.x;
    const int lane  = tid & 31;
    const int wseg  = tid >> 5;                 // 0..3, 128-col segment
    const int plane = blockIdx.y;
    const int r0    = blockIdx.x * RPB;

    const int segbase = wseg * 128;
    const int base    = segbase + lane * 4;
    const float* __restrict__ xp = x + (size_t)plane * H * W;
    const float* __restrict__ yp = y + (size_t)plane * H * W;

    const int  hcol   = (lane == 0) ? ((wseg == 0) ? 1 : segbase - 1)
                                    : ((wseg == 3) ? 510 : segbase + 128);
    const bool doHalo = (lane == 0) || (lane == 31);

    K k;
    k.twop = pk(2.0f, 2.0f);
    k.n2p  = pk(-2.0f, -2.0f);
    k.p18  = pk(18.0f, 18.0f);
    k.p9   = pk(9.0f, 9.0f);
    k.c1p  = pk(0.0081f, 0.0081f);   // 81*C1
    k.c2p  = pk(0.0729f, 0.0729f);   // 81*C2
    k.nhp  = pk(-0.5f, -0.5f);
    k.php  = pk(0.5f, 0.5f);

    RowR b0, b1, b2, b3;
    load_row(b0, xp, yp, refl(r0 - 1), base, hcol, doHalo);
    load_row(b1, xp, yp, r0,           base, hcol, doHalo);
    load_row(b2, xp, yp, r0 + 1,       base, hcol, doHalo);

    u64 acc0 = pk(0.0f, 0.0f), acc1 = pk(0.0f, 0.0f);
    #pragma unroll
    for (int j = 0; j < RPB; j += 4) {
        const int r = r0 + j;
        load_row(b3, xp, yp, refl(r + 2), base, hcol, doHalo);
        emit_pair(b0, b1, b2, b3, acc0, acc1, lane, wseg, k);   // rows r, r+1
        load_row(b0, xp, yp, refl(r + 3), base, hcol, doHalo);
        load_row(b1, xp, yp, refl(r + 4), base, hcol, doHalo);
        emit_pair(b2, b3, b0, b1, acc0, acc1, lane, wseg, k);   // rows r+2, r+3
        load_row(b2, xp, yp, refl(r + 5), base, hcol, doHalo);
    }

    // ---- block reduction ----
    u64 acc = add2(acc0, acc1);
    float alo, ahi; unpk(acc, alo, ahi);
    float accf = alo + ahi;
    #pragma unroll
    for (int o = 16; o > 0; o >>= 1)
        accf += __shfl_xor_sync(0xffffffffu, accf, o);

    __shared__ float wsum[4];
    __shared__ int   last_flag;
    if (lane == 0) wsum[wseg] = accf;
    __syncthreads();

    if (tid == 0) {
        float p = wsum[0] + wsum[1] + wsum[2] + wsum[3];
        g_partials[blockIdx.y * gridDim.x + blockIdx.x] = p;
        __threadfence();
        unsigned t = atomicAdd(&g_count, 1u);
        last_flag = (t == NBLOCKS - 1);
    }
    __syncthreads();

    if (last_flag) {
        double s = 0.0;
        for (int i = tid; i < NBLOCKS; i += 128)
            s += (double)__ldcg(&g_partials[i]);
        #pragma unroll
        for (int o = 16; o > 0; o >>= 1)
            s += __shfl_xor_sync(0xffffffffu, s, o);
        __shared__ double dsum[4];
        if (lane == 0) dsum[wseg] = s;
        __syncthreads();
        if (tid == 0) {
            double total = dsum[0] + dsum[1] + dsum[2] + dsum[3];
            out[0] = (float)(total / (double)((size_t)PLANES * H * W));
            g_count = 0;  // reset for next graph replay
        }
    }
}

extern "C" void kernel_launch(void* const* d_in, const int* in_sizes, int n_in,
                              void* d_out, int out_size) {
    const float* x = (const float*)d_in[0];
    const float* y = (const float*)d_in[1];
    float* out = (float*)d_out;

    dim3 grid(BLOCKS_X, PLANES);
    ssim_main<<<grid, 128>>>(x, y, out);
}

// round 8
// speedup vs baseline: 2.0054x; 2.0054x over previous
#include <cuda_runtime.h>
#include <cstdint>

// SSIM loss, NCHW (32,3,512,512) fp32, 3x3 box, reflect pad 1, scalar mean.
// R7: revert to R5 structure (best: 59.9us, regs 78, 6 blocks/SM), add
// zero-register L2 prefetch ~6 rows ahead so the distance-1 register pipeline
// only ever has to cover L2-hit latency, plus dual packed accumulators.

#define H 512
#define W 512
#define PLANES (32 * 3)
#define RPB 32
#define BLOCKS_X (H / RPB)           // 16
#define NBLOCKS (BLOCKS_X * PLANES)  // 1536

typedef unsigned long long u64;

__device__ float g_partials[NBLOCKS];
__device__ unsigned int g_count = 0;

__device__ __forceinline__ u64 pk(float lo, float hi) {
    u64 r; asm("mov.b64 %0, {%1, %2};" : "=l"(r) : "f"(lo), "f"(hi)); return r;
}
__device__ __forceinline__ void unpk(u64 v, float& lo, float& hi) {
    asm("mov.b64 {%0, %1}, %2;" : "=f"(lo), "=f"(hi) : "l"(v));
}
__device__ __forceinline__ u64 add2(u64 a, u64 b) {
    u64 d; asm("add.rn.f32x2 %0, %1, %2;" : "=l"(d) : "l"(a), "l"(b)); return d;
}
__device__ __forceinline__ u64 sub2(u64 a, u64 b) {
    u64 d; asm("sub.rn.f32x2 %0, %1, %2;" : "=l"(d) : "l"(a), "l"(b)); return d;
}
__device__ __forceinline__ u64 mul2(u64 a, u64 b) {
    u64 d; asm("mul.rn.f32x2 %0, %1, %2;" : "=l"(d) : "l"(a), "l"(b)); return d;
}
__device__ __forceinline__ u64 fma2(u64 a, u64 b, u64 c) {
    u64 d; asm("fma.rn.f32x2 %0, %1, %2, %3;" : "=l"(d) : "l"(a), "l"(b), "l"(c)); return d;
}
__device__ __forceinline__ float rcpf(float x) {
    float r; asm("rcp.approx.ftz.f32 %0, %1;" : "=f"(r) : "f"(x)); return r;
}
__device__ __forceinline__ void pf_l2(const float* p) {
    asm volatile("prefetch.global.L2 [%0];" :: "l"(p));
}

__device__ __forceinline__ int refl(int i) {
    // reflect pad of 1; valid for i in [-(H-1), 2H-2] (covers prefetch overshoot)
    if (i < 0) return -i;
    if (i > H - 1) return 2 * (H - 1) - i;
    return i;
}

// Raw row: packed x,y for 4 columns + halo scalars (lanes 0/31 only).
struct RowR { u64 X0, X1, Y0, Y1; float hX, hY; };

struct K { u64 twop, n2p, p18, p9, c1p, c2p, nhp, php; };

__device__ __forceinline__ void load_row(RowR& R,
                                         const float* __restrict__ xp,
                                         const float* __restrict__ yp,
                                         int rr, int base, int hcol, bool doHalo) {
    const float4 xv = *reinterpret_cast<const float4*>(xp + rr * W + base);
    const float4 yv = *reinterpret_cast<const float4*>(yp + rr * W + base);
    R.X0 = pk(xv.x, xv.y); R.X1 = pk(xv.z, xv.w);
    R.Y0 = pk(yv.x, yv.y); R.Y1 = pk(yv.z, yv.w);
    if (doHalo) {
        R.hX = __ldg(xp + rr * W + hcol);
        R.hY = __ldg(yp + rr * W + hcol);
    }
}

// SSIM on raw 3x3 window sums (packed pixel pair); /9 factors cancel:
//   n/d = (2A+81C1)(18 Sxy - 2A + 81C2) / ((B+C+81C1)(9(Sxx+Syy)-B-C+81C2))
__device__ __forceinline__ u64 ssim2(u64 Sx, u64 Sy, u64 Sxx, u64 Syy, u64 Sxy,
                                     const K& k) {
    u64 A  = mul2(Sx, Sy);
    u64 B  = mul2(Sx, Sx);
    u64 C  = mul2(Sy, Sy);
    u64 n1 = fma2(A, k.twop, k.c1p);
    u64 t  = fma2(A, k.n2p,  k.c2p);
    u64 n2 = fma2(Sxy, k.p18, t);
    u64 n  = mul2(n1, n2);
    u64 BC = add2(B, C);
    u64 d1 = add2(BC, k.c1p);
    u64 u  = sub2(k.c2p, BC);
    u64 d2 = fma2(add2(Sxx, Syy), k.p9, u);
    u64 d  = mul2(d1, d2);
    float dd0, dd1; unpk(d, dd0, dd1);
    u64 rp = pk(rcpf(dd0), rcpf(dd1));
    u64 q  = mul2(n, rp);
    return fma2(q, k.nhp, k.php);
}

// Horizontal packed 3-sum of vertical sums v0 (px 0,1), v1 (px 2,3), halo hv.
#define HQ(q)                                                                 \
    float a0_##q, a1_##q, a2_##q, a3_##q;                                     \
    unpk(v0_##q, a0_##q, a1_##q);                                             \
    unpk(v1_##q, a2_##q, a3_##q);                                             \
    float lv_##q = __shfl_up_sync(0xffffffffu, a3_##q, 1);                    \
    float rv_##q = __shfl_down_sync(0xffffffffu, a0_##q, 1);                  \
    if (lane == 0)  lv_##q = (wseg == 0) ? a1_##q : hv_##q;                   \
    if (lane == 31) rv_##q = (wseg == 3) ? a2_##q : hv_##q;                   \
    u64 mid_##q = pk(a1_##q, a2_##q);                                         \
    u64 h0_##q = add2(add2(pk(lv_##q, a0_##q), v0_##q), mid_##q);             \
    u64 h1_##q = add2(add2(mid_##q, v1_##q), pk(a3_##q, rv_##q));

__device__ __forceinline__ void emit(const RowR& A, const RowR& B, const RowR& C,
                                     u64& acc, int lane, int wseg, const K& k) {
    // vertical 3-sums; squares/products as FMA chains
    u64 v0_X  = add2(add2(A.X0, B.X0), C.X0);
    u64 v1_X  = add2(add2(A.X1, B.X1), C.X1);
    u64 v0_Y  = add2(add2(A.Y0, B.Y0), C.Y0);
    u64 v1_Y  = add2(add2(A.Y1, B.Y1), C.Y1);
    u64 v0_XX = fma2(A.X0, A.X0, fma2(B.X0, B.X0, mul2(C.X0, C.X0)));
    u64 v1_XX = fma2(A.X1, A.X1, fma2(B.X1, B.X1, mul2(C.X1, C.X1)));
    u64 v0_YY = fma2(A.Y0, A.Y0, fma2(B.Y0, B.Y0, mul2(C.Y0, C.Y0)));
    u64 v1_YY = fma2(A.Y1, A.Y1, fma2(B.Y1, B.Y1, mul2(C.Y1, C.Y1)));
    u64 v0_XY = fma2(A.X0, A.Y0, fma2(B.X0, B.Y0, mul2(C.X0, C.Y0)));
    u64 v1_XY = fma2(A.X1, A.Y1, fma2(B.X1, B.Y1, mul2(C.X1, C.Y1)));

    // halo vertical sums (meaningful on lanes 0/31 only)
    float hv_X  = A.hX + B.hX + C.hX;
    float hv_Y  = A.hY + B.hY + C.hY;
    float hv_XX = fmaf(A.hX, A.hX, fmaf(B.hX, B.hX, C.hX * C.hX));
    float hv_YY = fmaf(A.hY, A.hY, fmaf(B.hY, B.hY, C.hY * C.hY));
    float hv_XY = fmaf(A.hX, A.hY, fmaf(B.hX, B.hY, C.hX * C.hY));

    HQ(X) HQ(Y) HQ(XX) HQ(YY) HQ(XY)
    acc = add2(acc, ssim2(h0_X, h0_Y, h0_XX, h0_YY, h0_XY, k));
    acc = add2(acc, ssim2(h1_X, h1_Y, h1_XX, h1_YY, h1_XY, k));
}

__global__ __launch_bounds__(128)
void ssim_main(const float* __restrict__ x, const float* __restrict__ y,
               float* __restrict__ out) {
    const int tid   = threadIdx.x;
    const int lane  = tid & 31;
    const int wseg  = tid >> 5;                 // 0..3, 128-col segment
    const int plane = blockIdx.y;
    const int r0    = blockIdx.x * RPB;

    const int segbase = wseg * 128;
    const int base    = segbase + lane * 4;
    const float* __restrict__ xp = x + (size_t)plane * H * W;
    const float* __restrict__ yp = y + (size_t)plane * H * W;

    const int  hcol   = (lane == 0) ? ((wseg == 0) ? 1 : segbase - 1)
                                    : ((wseg == 3) ? 510 : segbase + 128);
    const bool doHalo = (lane == 0) || (lane == 31);
    // one prefetch per 128B L2 line: lanes 0,8,16,24 cover the warp's 512B row span
    const bool doPf   = ((lane & 7) == 0);
    const int  pfoff  = segbase + lane * 4;     // 16B-aligned, line-distinct per lane&7==0

    K k;
    k.twop = pk(2.0f, 2.0f);
    k.n2p  = pk(-2.0f, -2.0f);
    k.p18  = pk(18.0f, 18.0f);
    k.p9   = pk(9.0f, 9.0f);
    k.c1p  = pk(0.0081f, 0.0081f);   // 81*C1
    k.c2p  = pk(0.0729f, 0.0729f);   // 81*C2
    k.nhp  = pk(-0.5f, -0.5f);
    k.php  = pk(0.5f, 0.5f);

    // ---- pipelined 4-buffer ring: load row r+2 before emitting row r;
    //      L2 prefetch row r+6 so that load hits L2.
    RowR b0, b1, b2, b3;
    load_row(b0, xp, yp, refl(r0 - 1), base, hcol, doHalo);
    load_row(b1, xp, yp, r0,           base, hcol, doHalo);
    load_row(b2, xp, yp, r0 + 1,       base, hcol, doHalo);
    if (doPf) {
        #pragma unroll
        for (int p = 2; p <= 5; ++p) {
            pf_l2(xp + refl(r0 + p) * W + pfoff);
            pf_l2(yp + refl(r0 + p) * W + pfoff);
        }
    }

    u64 acc0 = pk(0.0f, 0.0f), acc1 = pk(0.0f, 0.0f);
    #pragma unroll
    for (int j = 0; j < RPB; j += 4) {
        const int rr = r0 + j;
        load_row(b3, xp, yp, refl(rr + 2), base, hcol, doHalo);
        if (doPf) { pf_l2(xp + refl(rr + 6) * W + pfoff); pf_l2(yp + refl(rr + 6) * W + pfoff); }
        emit(b0, b1, b2, acc0, lane, wseg, k);                 // row rr
        load_row(b0, xp, yp, refl(rr + 3), base, hcol, doHalo);
        if (doPf) { pf_l2(xp + refl(rr + 7) * W + pfoff); pf_l2(yp + refl(rr + 7) * W + pfoff); }
        emit(b1, b2, b3, acc1, lane, wseg, k);                 // row rr+1
        load_row(b1, xp, yp, refl(rr + 4), base, hcol, doHalo);
        if (doPf) { pf_l2(xp + refl(rr + 8) * W + pfoff); pf_l2(yp + refl(rr + 8) * W + pfoff); }
        emit(b2, b3, b0, acc0, lane, wseg, k);                 // row rr+2
        load_row(b2, xp, yp, refl(rr + 5), base, hcol, doHalo);
        if (doPf) { pf_l2(xp + refl(rr + 9) * W + pfoff); pf_l2(yp + refl(rr + 9) * W + pfoff); }
        emit(b3, b0, b1, acc1, lane, wseg, k);                 // row rr+3
    }

    // ---- block reduction ----
    u64 acc = add2(acc0, acc1);
    float alo, ahi; unpk(acc, alo, ahi);
    float accf = alo + ahi;
    #pragma unroll
    for (int o = 16; o > 0; o >>= 1)
        accf += __shfl_xor_sync(0xffffffffu, accf, o);

    __shared__ float wsum[4];
    __shared__ int   last_flag;
    if (lane == 0) wsum[wseg] = accf;
    __syncthreads();

    if (tid == 0) {
        float p = wsum[0] + wsum[1] + wsum[2] + wsum[3];
        g_partials[blockIdx.y * gridDim.x + blockIdx.x] = p;
        __threadfence();
        unsigned t = atomicAdd(&g_count, 1u);
        last_flag = (t == NBLOCKS - 1);
    }
    __syncthreads();

    if (last_flag) {
        double s = 0.0;
        for (int i = tid; i < NBLOCKS; i += 128)
            s += (double)__ldcg(&g_partials[i]);
        #pragma unroll
        for (int o = 16; o > 0; o >>= 1)
            s += __shfl_xor_sync(0xffffffffu, s, o);
        __shared__ double dsum[4];
        if (lane == 0) dsum[wseg] = s;
        __syncthreads();
        if (tid == 0) {
            double total = dsum[0] + dsum[1] + dsum[2] + dsum[3];
            out[0] = (float)(total / (double)((size_t)PLANES * H * W));
            g_count = 0;  // reset for next graph replay
        }
    }
}

extern "C" void kernel_launch(void* const* d_in, const int* in_sizes, int n_in,
                              void* d_out, int out_size) {
    const float* x = (const float*)d_in[0];
    const float* y = (const float*)d_in[1];
    float* out = (float*)d_out;

    dim3 grid(BLOCKS_X, PLANES);
    ssim_main<<<grid, 128>>>(x, y, out);
}